// round 12
// baseline (speedup 1.0000x reference)
#include <cuda_runtime.h>
#include <cuda_bf16.h>
#include <cstdint>

#define HWSZ 65536
#define DDIM 1536
#define TOKB_PART (64u*256u*1536u)

__device__ float g_qkv[8u*144u*65536u];
__device__ __nv_bfloat16 g_tokb[3u*TOKB_PART];   // q,k,v(hi) bf16 [part][bh][tok][d]
__device__ __nv_bfloat16 g_vlo[TOKB_PART];       // v residual
__device__ float g_rnorm[2u*16384u];
__device__ float g_oimg[8u*48u*65536u];

__device__ __forceinline__ uint32_t smem_u32(const void* p) {
    uint32_t a;
    asm("{ .reg .u64 t; cvta.to.shared.u64 t, %1; cvt.u32.u64 %0, t; }" : "=r"(a) : "l"(p));
    return a;
}
#define SW128(o) ((o) ^ (((o) >> 3) & 0x70))

__device__ __forceinline__ void cp16(uint32_t s, const void* g) {
    asm volatile("cp.async.cg.shared.global [%0], [%1], 16;" :: "r"(s), "l"(g));
}
#define CP_COMMIT() asm volatile("cp.async.commit_group;" ::: "memory")
#define CP_WAIT1()  asm volatile("cp.async.wait_group 1;" ::: "memory")
#define CP_WAIT0()  asm volatile("cp.async.wait_group 0;" ::: "memory")

__device__ __forceinline__ void ldsm_x4(uint32_t* r, uint32_t a) {
    asm volatile("ldmatrix.sync.aligned.m8n8.x4.shared.b16 {%0,%1,%2,%3}, [%4];"
                 : "=r"(r[0]), "=r"(r[1]), "=r"(r[2]), "=r"(r[3]) : "r"(a));
}
__device__ __forceinline__ void ldsm_x2(uint32_t* r, uint32_t a) {
    asm volatile("ldmatrix.sync.aligned.m8n8.x2.shared.b16 {%0,%1}, [%2];"
                 : "=r"(r[0]), "=r"(r[1]) : "r"(a));
}
__device__ __forceinline__ void ldsm_x2t(uint32_t* r, uint32_t a) {
    asm volatile("ldmatrix.sync.aligned.m8n8.x2.trans.shared.b16 {%0,%1}, [%2];"
                 : "=r"(r[0]), "=r"(r[1]) : "r"(a));
}
__device__ __forceinline__ void mma_bf16(float* c, const uint32_t* a, const uint32_t* b) {
    asm volatile(
        "mma.sync.aligned.m16n8k16.row.col.f32.bf16.bf16.f32 "
        "{%0,%1,%2,%3}, {%4,%5,%6,%7}, {%8,%9}, {%0,%1,%2,%3};"
        : "+f"(c[0]), "+f"(c[1]), "+f"(c[2]), "+f"(c[3])
        : "r"(a[0]), "r"(a[1]), "r"(a[2]), "r"(a[3]), "r"(b[0]), "r"(b[1]));
}
__device__ __forceinline__ void split_hl(float v, __nv_bfloat16& h, __nv_bfloat16& l) {
    h = __float2bfloat16(v);
    l = __float2bfloat16(v - __bfloat162float(h));
}

// ---------------------------------------------------------------------------
// K1 (HMMA v2): qkv 1x1 conv (unchanged)
// ---------------------------------------------------------------------------
__global__ __launch_bounds__(256) void k_qkv(const float* __restrict__ x,
                                             const float* __restrict__ wq) {
    extern __shared__ __align__(128) char smq[];
    char* Xhi = smq;
    char* Xlo = smq + 16384;
    char* Whi = smq + 32768;
    char* Wlo = smq + 51200;

    const int t = threadIdx.x;
    const int warp = t >> 5, lane = t & 31, lm = lane & 15;
    const int b = blockIdx.y;
    const int p0 = blockIdx.x * 128;

    for (int i = t; i < 144 * 48; i += 256) {
        int o = i / 48, c = i - o * 48;
        __nv_bfloat16 h, l; split_hl(wq[i], h, l);
        *(__nv_bfloat16*)(Whi + SW128(o * 128 + c * 2)) = h;
        *(__nv_bfloat16*)(Wlo + SW128(o * 128 + c * 2)) = l;
    }
    const float* xb = x + (size_t)b * 48 * HWSZ + p0;
#pragma unroll
    for (int r = 0; r < 6; r++) {
        int idx = t + 256 * r;
        int c = idx >> 5, f4 = idx & 31;
        float4 v = *reinterpret_cast<const float4*>(&xb[(size_t)c * HWSZ + f4 * 4]);
        int px = f4 * 4;
        __nv_bfloat16 h, l;
        split_hl(v.x, h, l);
        *(__nv_bfloat16*)(Xhi + SW128((px + 0) * 128 + c * 2)) = h;
        *(__nv_bfloat16*)(Xlo + SW128((px + 0) * 128 + c * 2)) = l;
        split_hl(v.y, h, l);
        *(__nv_bfloat16*)(Xhi + SW128((px + 1) * 128 + c * 2)) = h;
        *(__nv_bfloat16*)(Xlo + SW128((px + 1) * 128 + c * 2)) = l;
        split_hl(v.z, h, l);
        *(__nv_bfloat16*)(Xhi + SW128((px + 2) * 128 + c * 2)) = h;
        *(__nv_bfloat16*)(Xlo + SW128((px + 2) * 128 + c * 2)) = l;
        split_hl(v.w, h, l);
        *(__nv_bfloat16*)(Xhi + SW128((px + 3) * 128 + c * 2)) = h;
        *(__nv_bfloat16*)(Xlo + SW128((px + 3) * 128 + c * 2)) = l;
    }
    __syncthreads();

    const int warpM = warp >> 1, warpN = warp & 1;
    const int m0 = warpM * 32, n0 = warpN * 72;
    const uint32_t aXh = smem_u32(Xhi), aXl = smem_u32(Xlo);
    const uint32_t aWh = smem_u32(Whi), aWl = smem_u32(Wlo);

    float acc[2][9][4];
#pragma unroll
    for (int i = 0; i < 2; i++)
#pragma unroll
        for (int j = 0; j < 9; j++)
#pragma unroll
            for (int q = 0; q < 4; q++) acc[i][j][q] = 0.f;

#pragma unroll
    for (int ks = 0; ks < 3; ks++) {
        int k0 = ks * 16;
        uint32_t ah[2][4], al[2][4];
#pragma unroll
        for (int i = 0; i < 2; i++) {
            int row = m0 + i * 16 + lm;
            ldsm_x4(ah[i], aXh + SW128(row * 128 + k0 * 2 + ((lane >> 4) << 4)));
            ldsm_x4(al[i], aXl + SW128(row * 128 + k0 * 2 + ((lane >> 4) << 4)));
        }
        uint32_t bh2[9][2], bl2[9][2];
#pragma unroll
        for (int j = 0; j < 9; j++) {
            int row = n0 + j * 8 + (lm & 7);
            ldsm_x2(bh2[j], aWh + SW128(row * 128 + (k0 + ((lm >> 3) << 3)) * 2));
            ldsm_x2(bl2[j], aWl + SW128(row * 128 + (k0 + ((lm >> 3) << 3)) * 2));
        }
#pragma unroll
        for (int i = 0; i < 2; i++)
#pragma unroll
            for (int j = 0; j < 9; j++) {
                mma_bf16(acc[i][j], ah[i], bh2[j]);
                mma_bf16(acc[i][j], ah[i], bl2[j]);
                mma_bf16(acc[i][j], al[i], bh2[j]);
            }
    }

    float* outb = g_qkv + (size_t)b * 144 * HWSZ + p0;
#pragma unroll
    for (int i = 0; i < 2; i++) {
        int pxA = m0 + i * 16 + (lane >> 2);
        int pxB = pxA + 8;
#pragma unroll
        for (int j = 0; j < 9; j++) {
            int o = n0 + j * 8 + ((lane & 3) << 1);
            outb[(size_t)o * HWSZ + pxA]       = acc[i][j][0];
            outb[(size_t)(o + 1) * HWSZ + pxA] = acc[i][j][1];
            outb[(size_t)o * HWSZ + pxB]       = acc[i][j][2];
            outb[(size_t)(o + 1) * HWSZ + pxB] = acc[i][j][3];
        }
    }
}

// ---------------------------------------------------------------------------
// K2: depthwise 3x3 via smem row cache (unchanged)
// ---------------------------------------------------------------------------
__global__ __launch_bounds__(256) void k_dw(const float* __restrict__ wdw) {
    __shared__ float rows[34 * 259];
    const int t = threadIdx.x;
    const int ch = blockIdx.x, b = blockIdx.y, z = blockIdx.z;
    const float* src = g_qkv + ((size_t)(b * 144 + ch)) * HWSZ;

    float wd[9];
#pragma unroll
    for (int j = 0; j < 9; j++) wd[j] = wdw[ch * 9 + j];

    const int y0 = z * 32;
    for (int idx = t; idx < 34 * 258; idx += 256) {
        int r = idx / 258, col = idx - r * 258;
        int y = y0 - 1 + r, x = col - 1;
        float v = 0.f;
        if ((unsigned)y < 256u && (unsigned)x < 256u) v = src[y * 256 + x];
        rows[r * 259 + col] = v;
    }
    __syncthreads();

    const int fx = t >> 4, fy = t & 15;
    float ov[2][16];
#pragma unroll
    for (int hl = 0; hl < 2; hl++) {
        const float* r0 = rows + (hl * 16 + fy) * 259 + fx;
        const float* r1 = r0 + 259;
        const float* r2 = r1 + 259;
#pragma unroll
        for (int ww = 0; ww < 16; ww++) {
            int c0 = ww * 16;
            float v = wd[0] * r0[c0] + wd[1] * r0[c0 + 1] + wd[2] * r0[c0 + 2]
                    + wd[3] * r1[c0] + wd[4] * r1[c0 + 1] + wd[5] * r1[c0 + 2]
                    + wd[6] * r2[c0] + wd[7] * r2[c0 + 1] + wd[8] * r2[c0 + 2];
            ov[hl][ww] = v;
        }
    }

    const int part = ch / 48, cc = ch % 48;
    const int head = cc / 6, c = cc % 6;
    const size_t off = (size_t)t * DDIM + c * 256 + z * 32;
    __nv_bfloat16* dst = g_tokb + (size_t)part * TOKB_PART +
                         ((size_t)((b * 8 + head) * 256)) * DDIM + off;
    __nv_bfloat16 hb[32], lb[32];
#pragma unroll
    for (int hl = 0; hl < 2; hl++)
#pragma unroll
        for (int ww = 0; ww < 16; ww++)
            split_hl(ov[hl][ww], hb[hl * 16 + ww], lb[hl * 16 + ww]);
    uint4* d4 = (uint4*)dst;
    d4[0] = ((uint4*)hb)[0]; d4[1] = ((uint4*)hb)[1];
    d4[2] = ((uint4*)hb)[2]; d4[3] = ((uint4*)hb)[3];
    if (part == 2) {
        uint4* l4 = (uint4*)(g_vlo + ((size_t)((b * 8 + head) * 256)) * DDIM + off);
        l4[0] = ((uint4*)lb)[0]; l4[1] = ((uint4*)lb)[1];
        l4[2] = ((uint4*)lb)[2]; l4[3] = ((uint4*)lb)[3];
    }
}

// ---------------------------------------------------------------------------
// K2b: reciprocal L2 norms (unchanged)
// ---------------------------------------------------------------------------
__global__ __launch_bounds__(256) void k_norm() {
    int t = threadIdx.x;
    int w = t >> 5, lane = t & 31;
    int rid = blockIdx.x * 8 + w;
    const __nv_bfloat16* p = g_tokb + (size_t)rid * DDIM;
    float ss = 0.f;
#pragma unroll
    for (int i = 0; i < 48; i++) {
        float v = __bfloat162float(p[lane + 32 * i]);
        ss += v * v;
    }
#pragma unroll
    for (int off = 16; off; off >>= 1) ss += __shfl_xor_sync(0xffffffffu, ss, off);
    if (lane == 0) g_rnorm[rid] = 1.0f / fmaxf(sqrtf(ss), 1e-12f);
}

// ---------------------------------------------------------------------------
// K3: attention. Phase 1: cp.async pipelined (R11). Phase 2: 32x32 warp tiles.
// ---------------------------------------------------------------------------
__global__ __launch_bounds__(256, 1) void k_attn(const float* __restrict__ temperature) {
    extern __shared__ __align__(128) char sm[];
    char* Ahi = sm;
    char* Alo = sm + 67584;
    char* Tc  = sm + 135168;
    float* rqs  = (float*)(sm + 200704);
    float* rks  = rqs + 128;
    float* rsp  = rks + 256;
    float* rsum = rsp + 512;

    const int t = threadIdx.x;
    const int warp = t >> 5, lane = t & 31;
    const int mt = blockIdx.x;
    const int bh = blockIdx.y;
    const int head = bh & 7;
    const int b = bh >> 3;

    const __nv_bfloat16* gq = g_tokb + (size_t)bh * 256 * DDIM;
    const __nv_bfloat16* gk = g_tokb + (size_t)TOKB_PART + (size_t)bh * 256 * DDIM;
    const __nv_bfloat16* gv = g_tokb + 2u * (size_t)TOKB_PART + (size_t)bh * 256 * DDIM;
    const __nv_bfloat16* gvl = g_vlo + (size_t)bh * 256 * DDIM;

    const uint32_t aAh = smem_u32(Ahi);
    const uint32_t aAl = smem_u32(Alo);
    const uint32_t aV  = smem_u32(Tc);
    const uint32_t aVl = aV + 32768;

    if (t < 128) {
        int n = (t >> 3) * 16 + mt * 8 + (t & 7);
        rqs[t] = g_rnorm[bh * 256 + n] * temperature[head];
    }
    rks[t] = g_rnorm[16384 + bh * 256 + t];

    const int warpM = warp >> 2, warpN = warp & 3;
    float acc[4][8][4];
#pragma unroll
    for (int i = 0; i < 4; i++)
#pragma unroll
        for (int j = 0; j < 8; j++)
#pragma unroll
            for (int q = 0; q < 4; q++) acc[i][j][q] = 0.f;

    // prologue: chunk 0 -> B0 (aV)
    {
#pragma unroll
        for (int i = 0; i < 4; i++) {
            int s = t + 256 * i; int r = s >> 3, cs = s & 7;
            int n = (r >> 3) * 16 + mt * 8 + (r & 7);
            cp16(aV + SW128(r * 128 + cs * 16), gq + (size_t)n * DDIM + cs * 8);
        }
#pragma unroll
        for (int i = 0; i < 8; i++) {
            int s = t + 256 * i; int m2 = s >> 3, cs = s & 7;
            cp16(aV + 16384 + SW128(m2 * 128 + cs * 16), gk + (size_t)m2 * DDIM + cs * 8);
        }
        CP_COMMIT();
    }

    // ---------------- Phase 1: S = Q K^T (pipelined) ----------------
#pragma unroll 1
    for (int ck = 0; ck < 24; ck++) {
        uint32_t aBuf = (ck & 1) ? aAh : aV;
        if (ck < 23) {
            int d0n = (ck + 1) * 64;
            uint32_t aNext = ((ck + 1) & 1) ? aAh : aV;
#pragma unroll
            for (int i = 0; i < 4; i++) {
                int s = t + 256 * i; int r = s >> 3, cs = s & 7;
                int n = (r >> 3) * 16 + mt * 8 + (r & 7);
                cp16(aNext + SW128(r * 128 + cs * 16), gq + (size_t)n * DDIM + d0n + cs * 8);
            }
#pragma unroll
            for (int i = 0; i < 8; i++) {
                int s = t + 256 * i; int m2 = s >> 3, cs = s & 7;
                cp16(aNext + 16384 + SW128(m2 * 128 + cs * 16),
                     gk + (size_t)m2 * DDIM + d0n + cs * 8);
            }
            CP_COMMIT();
            CP_WAIT1();
        } else {
            CP_WAIT0();
        }
        __syncthreads();

        int lm = lane & 15;
#pragma unroll
        for (int kk = 0; kk < 4; kk++) {
            int k0 = kk * 16;
            uint32_t af[4][4];
#pragma unroll
            for (int i = 0; i < 4; i++) {
                int row = warpM * 64 + i * 16 + lm;
                ldsm_x4(af[i], aBuf + SW128(row * 128 + k0 * 2 + ((lane >> 4) << 4)));
            }
            uint32_t bfg[8][2];
#pragma unroll
            for (int j = 0; j < 8; j++) {
                int row = warpN * 64 + j * 8 + (lm & 7);
                ldsm_x2(bfg[j], aBuf + 16384 + SW128(row * 128 + (k0 + ((lm >> 3) << 3)) * 2));
            }
#pragma unroll
            for (int i = 0; i < 4; i++)
#pragma unroll
                for (int j = 0; j < 8; j++) mma_bf16(acc[i][j], af[i], bfg[j]);
        }
        __syncthreads();
    }

    // -------- Epilogue 1: exp, rowsum, A -> smem hi+lo --------
#pragma unroll
    for (int i = 0; i < 4; i++) {
        int m0 = warpM * 64 + i * 16 + (lane >> 2);
        int m1 = m0 + 8;
        float q0 = rqs[m0], q1 = rqs[m1];
        float r0 = 0.f, r1 = 0.f;
#pragma unroll
        for (int j = 0; j < 8; j++) {
            int n0 = warpN * 64 + j * 8 + ((lane & 3) << 1);
            float k0v = rks[n0], k1v = rks[n0 + 1];
            float e00 = __expf(acc[i][j][0] * q0 * k0v);
            float e01 = __expf(acc[i][j][1] * q0 * k1v);
            float e10 = __expf(acc[i][j][2] * q1 * k0v);
            float e11 = __expf(acc[i][j][3] * q1 * k1v);
            r0 += e00 + e01; r1 += e10 + e11;
            uint32_t p0, p1;
            asm("cvt.rn.bf16x2.f32 %0, %1, %2;" : "=r"(p0) : "f"(e01), "f"(e00));
            asm("cvt.rn.bf16x2.f32 %0, %1, %2;" : "=r"(p1) : "f"(e11), "f"(e10));
            float h00 = __uint_as_float(p0 << 16),  h01 = __uint_as_float(p0 & 0xFFFF0000u);
            float h10 = __uint_as_float(p1 << 16),  h11 = __uint_as_float(p1 & 0xFFFF0000u);
            uint32_t q0p, q1p;
            asm("cvt.rn.bf16x2.f32 %0, %1, %2;" : "=r"(q0p) : "f"(e01 - h01), "f"(e00 - h00));
            asm("cvt.rn.bf16x2.f32 %0, %1, %2;" : "=r"(q1p) : "f"(e11 - h11), "f"(e10 - h10));
            *(uint32_t*)(Ahi + m0 * 528 + n0 * 2) = p0;
            *(uint32_t*)(Ahi + m1 * 528 + n0 * 2) = p1;
            *(uint32_t*)(Alo + m0 * 528 + n0 * 2) = q0p;
            *(uint32_t*)(Alo + m1 * 528 + n0 * 2) = q1p;
        }
        r0 += __shfl_xor_sync(0xffffffffu, r0, 1);
        r0 += __shfl_xor_sync(0xffffffffu, r0, 2);
        r1 += __shfl_xor_sync(0xffffffffu, r1, 1);
        r1 += __shfl_xor_sync(0xffffffffu, r1, 2);
        if ((lane & 3) == 0) {
            rsp[warpN * 128 + m0] = r0;
            rsp[warpN * 128 + m1] = r1;
        }
    }
    __syncthreads();
    if (t < 128) rsum[t] = 1.0f / (rsp[t] + rsp[128 + t] + rsp[256 + t] + rsp[384 + t] + 1.0f);
    __syncthreads();

    // -------- Phase 2: O = Ahi*Vhi + Ahi*Vlo + Alo*Vhi, 32x32 warp tiles --------
    float* oimg_base = g_oimg + ((size_t)(b * 48 + head * 6)) * HWSZ;
    const int fy0 = mt * 8;
    const int lm = lane & 15;
    const int warpR = warp >> 1, warpC = warp & 1;   // 4 row-groups x 2 col-groups
    const int m0r = warpR * 32;
#pragma unroll 1
    for (int ck = 0; ck < 24; ck++) {
        int d0 = ck * 64;
#pragma unroll
        for (int i = 0; i < 8; i++) {
            int s = t + 256 * i; int m2 = s >> 3, cs = s & 7;
            uint4 v = *(const uint4*)(gv + (size_t)m2 * DDIM + d0 + cs * 8);
            *(uint4*)(Tc + SW128(m2 * 128 + cs * 16)) = v;
            uint4 vl = *(const uint4*)(gvl + (size_t)m2 * DDIM + d0 + cs * 8);
            *(uint4*)(Tc + 32768 + SW128(m2 * 128 + cs * 16)) = vl;
        }
        __syncthreads();

        float oacc[2][4][4];
#pragma unroll
        for (int i = 0; i < 2; i++)
#pragma unroll
            for (int j = 0; j < 4; j++)
#pragma unroll
                for (int q = 0; q < 4; q++) oacc[i][j][q] = 0.f;

#pragma unroll 1
        for (int kk = 0; kk < 16; kk++) {
            int n0 = kk * 16;
            uint32_t afh[2][4], afl[2][4];
#pragma unroll
            for (int i = 0; i < 2; i++) {
                int row = m0r + i * 16 + lm;
                ldsm_x4(afh[i], aAh + row * 528 + (n0 + ((lane >> 4) << 3)) * 2);
                ldsm_x4(afl[i], aAl + row * 528 + (n0 + ((lane >> 4) << 3)) * 2);
            }
#pragma unroll
            for (int j = 0; j < 4; j++) {
                int jj = warpC * 4 + j;
                uint32_t bh2[2], bl2[2];
                ldsm_x2t(bh2, aV + SW128((n0 + lm) * 128 + jj * 16));
                ldsm_x2t(bl2, aVl + SW128((n0 + lm) * 128 + jj * 16));
#pragma unroll
                for (int i = 0; i < 2; i++) {
                    mma_bf16(oacc[i][j], afh[i], bh2);
                    mma_bf16(oacc[i][j], afh[i], bl2);
                    mma_bf16(oacc[i][j], afl[i], bh2);
                }
            }
        }
        __syncthreads();

        float* stg = (float*)Tc;
#pragma unroll
        for (int i = 0; i < 2; i++) {
            int r0 = m0r + i * 16 + (lane >> 2), r1 = r0 + 8;
            float s0 = rsum[r0], s1 = rsum[r1];
            int fx0 = r0 >> 3, fyl0 = r0 & 7;
            int fx1 = r1 >> 3, fyl1 = r1 & 7;
#pragma unroll
            for (int j = 0; j < 4; j++) {
                int cd = warpC * 32 + j * 8 + ((lane & 3) << 1);
                int hl = cd >> 4, ww = cd & 15;
                stg[(hl * 8 + fyl0) * 260 + ww * 16 + fx0]       = oacc[i][j][0] * s0;
                stg[(hl * 8 + fyl0) * 260 + (ww + 1) * 16 + fx0] = oacc[i][j][1] * s0;
                stg[(hl * 8 + fyl1) * 260 + ww * 16 + fx1]       = oacc[i][j][2] * s1;
                stg[(hl * 8 + fyl1) * 260 + (ww + 1) * 16 + fx1] = oacc[i][j][3] * s1;
            }
        }
        __syncthreads();
        int c = ck >> 2, hh0 = (ck & 3) * 4;
#pragma unroll
        for (int rr = 0; rr < 32; rr++) {
            int y = (hh0 + (rr >> 3)) * 16 + fy0 + (rr & 7);
            oimg_base[((size_t)c * 256 + y) * 256 + t] = stg[rr * 260 + t];
        }
        __syncthreads();
    }
}

// ---------------------------------------------------------------------------
// K4: project_out 1x1 conv (scalar, unchanged)
// ---------------------------------------------------------------------------
__global__ __launch_bounds__(256) void k_proj(const float* __restrict__ wp,
                                              float* __restrict__ out) {
    __shared__ float ws[48 * 48];
    __shared__ float xs[48 * 64];
    int t = threadIdx.x;
    int b = blockIdx.y;
    int p0 = blockIdx.x * 64;

    for (int i = t; i < 48 * 48; i += 256) ws[i] = wp[i];
    const float* xb = g_oimg + (size_t)b * 48 * HWSZ + p0;
    for (int i = t; i < 48 * 64; i += 256) {
        int c = i >> 6, px = i & 63;
        xs[c * 64 + px] = xb[(size_t)c * HWSZ + px];
    }
    __syncthreads();

    int pxg = t & 15, og = t >> 4;
    float acc[3][4];
#pragma unroll
    for (int j = 0; j < 3; j++)
#pragma unroll
        for (int ii = 0; ii < 4; ii++) acc[j][ii] = 0.f;

#pragma unroll 4
    for (int k = 0; k < 48; k++) {
        float4 xv = *reinterpret_cast<const float4*>(&xs[k * 64 + pxg * 4]);
#pragma unroll
        for (int j = 0; j < 3; j++) {
            float w = ws[(og * 3 + j) * 48 + k];
            acc[j][0] += w * xv.x; acc[j][1] += w * xv.y;
            acc[j][2] += w * xv.z; acc[j][3] += w * xv.w;
        }
    }
    float* ob = out + (size_t)b * 48 * HWSZ + p0 + pxg * 4;
#pragma unroll
    for (int j = 0; j < 3; j++) {
        int o = og * 3 + j;
        float4 v = make_float4(acc[j][0], acc[j][1], acc[j][2], acc[j][3]);
        *reinterpret_cast<float4*>(&ob[(size_t)o * HWSZ]) = v;
    }
}

extern "C" void kernel_launch(void* const* d_in, const int* in_sizes, int n_in,
                              void* d_out, int out_size) {
    const float* x      = (const float*)d_in[0];
    const float* w_qkv  = (const float*)d_in[1];
    const float* w_dw   = (const float*)d_in[2];
    const float* w_proj = (const float*)d_in[3];
    const float* temp   = (const float*)d_in[4];
    float* out = (float*)d_out;

    cudaFuncSetAttribute(k_attn, cudaFuncAttributeMaxDynamicSharedMemorySize, 208 * 1024);
    cudaFuncSetAttribute(k_qkv, cudaFuncAttributeMaxDynamicSharedMemorySize, 72 * 1024);

    k_qkv<<<dim3(512, 8), 256, 69632>>>(x, w_qkv);
    k_dw<<<dim3(144, 8, 8), 256>>>(w_dw);
    k_norm<<<4096, 256>>>();
    k_attn<<<dim3(2, 64), 256, 204800>>>(temp);
    k_proj<<<dim3(1024, 8), 256>>>(w_proj, out);
}

// round 13
// speedup vs baseline: 1.0838x; 1.0838x over previous
#include <cuda_runtime.h>
#include <cuda_bf16.h>
#include <cstdint>

#define HWSZ 65536
#define DDIM 1536
#define TOKB_PART (64u*256u*1536u)

__device__ float g_qkv[8u*144u*65536u];
__device__ __nv_bfloat16 g_tokb[3u*TOKB_PART];   // q,k,v(hi) bf16 [part][bh][tok][d]
__device__ __nv_bfloat16 g_vlo[TOKB_PART];       // v residual
__device__ float g_rnorm[2u*16384u];
__device__ float g_oimg[8u*48u*65536u];

__device__ __forceinline__ uint32_t smem_u32(const void* p) {
    uint32_t a;
    asm("{ .reg .u64 t; cvta.to.shared.u64 t, %1; cvt.u32.u64 %0, t; }" : "=r"(a) : "l"(p));
    return a;
}
#define SW128(o) ((o) ^ (((o) >> 3) & 0x70))
#define SW64(o)  ((o) ^ (((o) >> 3) & 0x30))

__device__ __forceinline__ void cp16(uint32_t s, const void* g) {
    asm volatile("cp.async.cg.shared.global [%0], [%1], 16;" :: "r"(s), "l"(g));
}
#define CP_COMMIT() asm volatile("cp.async.commit_group;" ::: "memory")
#define CP_WAIT1()  asm volatile("cp.async.wait_group 1;" ::: "memory")
#define CP_WAIT0()  asm volatile("cp.async.wait_group 0;" ::: "memory")

__device__ __forceinline__ void ldsm_x4(uint32_t* r, uint32_t a) {
    asm volatile("ldmatrix.sync.aligned.m8n8.x4.shared.b16 {%0,%1,%2,%3}, [%4];"
                 : "=r"(r[0]), "=r"(r[1]), "=r"(r[2]), "=r"(r[3]) : "r"(a));
}
__device__ __forceinline__ void ldsm_x2(uint32_t* r, uint32_t a) {
    asm volatile("ldmatrix.sync.aligned.m8n8.x2.shared.b16 {%0,%1}, [%2];"
                 : "=r"(r[0]), "=r"(r[1]) : "r"(a));
}
__device__ __forceinline__ void ldsm_x2t(uint32_t* r, uint32_t a) {
    asm volatile("ldmatrix.sync.aligned.m8n8.x2.trans.shared.b16 {%0,%1}, [%2];"
                 : "=r"(r[0]), "=r"(r[1]) : "r"(a));
}
__device__ __forceinline__ void mma_bf16(float* c, const uint32_t* a, const uint32_t* b) {
    asm volatile(
        "mma.sync.aligned.m16n8k16.row.col.f32.bf16.bf16.f32 "
        "{%0,%1,%2,%3}, {%4,%5,%6,%7}, {%8,%9}, {%0,%1,%2,%3};"
        : "+f"(c[0]), "+f"(c[1]), "+f"(c[2]), "+f"(c[3])
        : "r"(a[0]), "r"(a[1]), "r"(a[2]), "r"(a[3]), "r"(b[0]), "r"(b[1]));
}
__device__ __forceinline__ void split_hl(float v, __nv_bfloat16& h, __nv_bfloat16& l) {
    h = __float2bfloat16(v);
    l = __float2bfloat16(v - __bfloat162float(h));
}

// ---------------------------------------------------------------------------
// K1 (HMMA v2): qkv 1x1 conv (unchanged)
// ---------------------------------------------------------------------------
__global__ __launch_bounds__(256) void k_qkv(const float* __restrict__ x,
                                             const float* __restrict__ wq) {
    extern __shared__ __align__(128) char smq[];
    char* Xhi = smq;
    char* Xlo = smq + 16384;
    char* Whi = smq + 32768;
    char* Wlo = smq + 51200;

    const int t = threadIdx.x;
    const int warp = t >> 5, lane = t & 31, lm = lane & 15;
    const int b = blockIdx.y;
    const int p0 = blockIdx.x * 128;

    for (int i = t; i < 144 * 48; i += 256) {
        int o = i / 48, c = i - o * 48;
        __nv_bfloat16 h, l; split_hl(wq[i], h, l);
        *(__nv_bfloat16*)(Whi + SW128(o * 128 + c * 2)) = h;
        *(__nv_bfloat16*)(Wlo + SW128(o * 128 + c * 2)) = l;
    }
    const float* xb = x + (size_t)b * 48 * HWSZ + p0;
#pragma unroll
    for (int r = 0; r < 6; r++) {
        int idx = t + 256 * r;
        int c = idx >> 5, f4 = idx & 31;
        float4 v = *reinterpret_cast<const float4*>(&xb[(size_t)c * HWSZ + f4 * 4]);
        int px = f4 * 4;
        __nv_bfloat16 h, l;
        split_hl(v.x, h, l);
        *(__nv_bfloat16*)(Xhi + SW128((px + 0) * 128 + c * 2)) = h;
        *(__nv_bfloat16*)(Xlo + SW128((px + 0) * 128 + c * 2)) = l;
        split_hl(v.y, h, l);
        *(__nv_bfloat16*)(Xhi + SW128((px + 1) * 128 + c * 2)) = h;
        *(__nv_bfloat16*)(Xlo + SW128((px + 1) * 128 + c * 2)) = l;
        split_hl(v.z, h, l);
        *(__nv_bfloat16*)(Xhi + SW128((px + 2) * 128 + c * 2)) = h;
        *(__nv_bfloat16*)(Xlo + SW128((px + 2) * 128 + c * 2)) = l;
        split_hl(v.w, h, l);
        *(__nv_bfloat16*)(Xhi + SW128((px + 3) * 128 + c * 2)) = h;
        *(__nv_bfloat16*)(Xlo + SW128((px + 3) * 128 + c * 2)) = l;
    }
    __syncthreads();

    const int warpM = warp >> 1, warpN = warp & 1;
    const int m0 = warpM * 32, n0 = warpN * 72;
    const uint32_t aXh = smem_u32(Xhi), aXl = smem_u32(Xlo);
    const uint32_t aWh = smem_u32(Whi), aWl = smem_u32(Wlo);

    float acc[2][9][4];
#pragma unroll
    for (int i = 0; i < 2; i++)
#pragma unroll
        for (int j = 0; j < 9; j++)
#pragma unroll
            for (int q = 0; q < 4; q++) acc[i][j][q] = 0.f;

#pragma unroll
    for (int ks = 0; ks < 3; ks++) {
        int k0 = ks * 16;
        uint32_t ah[2][4], al[2][4];
#pragma unroll
        for (int i = 0; i < 2; i++) {
            int row = m0 + i * 16 + lm;
            ldsm_x4(ah[i], aXh + SW128(row * 128 + k0 * 2 + ((lane >> 4) << 4)));
            ldsm_x4(al[i], aXl + SW128(row * 128 + k0 * 2 + ((lane >> 4) << 4)));
        }
        uint32_t bh2[9][2], bl2[9][2];
#pragma unroll
        for (int j = 0; j < 9; j++) {
            int row = n0 + j * 8 + (lm & 7);
            ldsm_x2(bh2[j], aWh + SW128(row * 128 + (k0 + ((lm >> 3) << 3)) * 2));
            ldsm_x2(bl2[j], aWl + SW128(row * 128 + (k0 + ((lm >> 3) << 3)) * 2));
        }
#pragma unroll
        for (int i = 0; i < 2; i++)
#pragma unroll
            for (int j = 0; j < 9; j++) {
                mma_bf16(acc[i][j], ah[i], bh2[j]);
                mma_bf16(acc[i][j], ah[i], bl2[j]);
                mma_bf16(acc[i][j], al[i], bh2[j]);
            }
    }

    float* outb = g_qkv + (size_t)b * 144 * HWSZ + p0;
#pragma unroll
    for (int i = 0; i < 2; i++) {
        int pxA = m0 + i * 16 + (lane >> 2);
        int pxB = pxA + 8;
#pragma unroll
        for (int j = 0; j < 9; j++) {
            int o = n0 + j * 8 + ((lane & 3) << 1);
            outb[(size_t)o * HWSZ + pxA]       = acc[i][j][0];
            outb[(size_t)(o + 1) * HWSZ + pxA] = acc[i][j][1];
            outb[(size_t)o * HWSZ + pxB]       = acc[i][j][2];
            outb[(size_t)(o + 1) * HWSZ + pxB] = acc[i][j][3];
        }
    }
}

// ---------------------------------------------------------------------------
// K2: depthwise 3x3 via smem row cache (unchanged)
// ---------------------------------------------------------------------------
__global__ __launch_bounds__(256) void k_dw(const float* __restrict__ wdw) {
    __shared__ float rows[34 * 259];
    const int t = threadIdx.x;
    const int ch = blockIdx.x, b = blockIdx.y, z = blockIdx.z;
    const float* src = g_qkv + ((size_t)(b * 144 + ch)) * HWSZ;

    float wd[9];
#pragma unroll
    for (int j = 0; j < 9; j++) wd[j] = wdw[ch * 9 + j];

    const int y0 = z * 32;
    for (int idx = t; idx < 34 * 258; idx += 256) {
        int r = idx / 258, col = idx - r * 258;
        int y = y0 - 1 + r, x = col - 1;
        float v = 0.f;
        if ((unsigned)y < 256u && (unsigned)x < 256u) v = src[y * 256 + x];
        rows[r * 259 + col] = v;
    }
    __syncthreads();

    const int fx = t >> 4, fy = t & 15;
    float ov[2][16];
#pragma unroll
    for (int hl = 0; hl < 2; hl++) {
        const float* r0 = rows + (hl * 16 + fy) * 259 + fx;
        const float* r1 = r0 + 259;
        const float* r2 = r1 + 259;
#pragma unroll
        for (int ww = 0; ww < 16; ww++) {
            int c0 = ww * 16;
            float v = wd[0] * r0[c0] + wd[1] * r0[c0 + 1] + wd[2] * r0[c0 + 2]
                    + wd[3] * r1[c0] + wd[4] * r1[c0 + 1] + wd[5] * r1[c0 + 2]
                    + wd[6] * r2[c0] + wd[7] * r2[c0 + 1] + wd[8] * r2[c0 + 2];
            ov[hl][ww] = v;
        }
    }

    const int part = ch / 48, cc = ch % 48;
    const int head = cc / 6, c = cc % 6;
    const size_t off = (size_t)t * DDIM + c * 256 + z * 32;
    __nv_bfloat16* dst = g_tokb + (size_t)part * TOKB_PART +
                         ((size_t)((b * 8 + head) * 256)) * DDIM + off;
    __nv_bfloat16 hb[32], lb[32];
#pragma unroll
    for (int hl = 0; hl < 2; hl++)
#pragma unroll
        for (int ww = 0; ww < 16; ww++)
            split_hl(ov[hl][ww], hb[hl * 16 + ww], lb[hl * 16 + ww]);
    uint4* d4 = (uint4*)dst;
    d4[0] = ((uint4*)hb)[0]; d4[1] = ((uint4*)hb)[1];
    d4[2] = ((uint4*)hb)[2]; d4[3] = ((uint4*)hb)[3];
    if (part == 2) {
        uint4* l4 = (uint4*)(g_vlo + ((size_t)((b * 8 + head) * 256)) * DDIM + off);
        l4[0] = ((uint4*)lb)[0]; l4[1] = ((uint4*)lb)[1];
        l4[2] = ((uint4*)lb)[2]; l4[3] = ((uint4*)lb)[3];
    }
}

// ---------------------------------------------------------------------------
// K2b: reciprocal L2 norms (unchanged)
// ---------------------------------------------------------------------------
__global__ __launch_bounds__(256) void k_norm() {
    int t = threadIdx.x;
    int w = t >> 5, lane = t & 31;
    int rid = blockIdx.x * 8 + w;
    const __nv_bfloat16* p = g_tokb + (size_t)rid * DDIM;
    float ss = 0.f;
#pragma unroll
    for (int i = 0; i < 48; i++) {
        float v = __bfloat162float(p[lane + 32 * i]);
        ss += v * v;
    }
#pragma unroll
    for (int off = 16; off; off >>= 1) ss += __shfl_xor_sync(0xffffffffu, ss, off);
    if (lane == 0) g_rnorm[rid] = 1.0f / fmaxf(sqrtf(ss), 1e-12f);
}

// ---------------------------------------------------------------------------
// K3: attention. Phase 1: cp.async pipelined (R11).
// Phase 2: cp.async pipelined 32-d sub-chunks, 2-stage V ring in Tc (SW64),
// dedicated OSTG staging region.
// smem: Ahi 67584 | Alo 67584 | Tc 65536 | OSTG 16640 | scalars 4096 = 221440
// ---------------------------------------------------------------------------
__global__ __launch_bounds__(256, 1) void k_attn(const float* __restrict__ temperature) {
    extern __shared__ __align__(128) char sm[];
    char* Ahi = sm;
    char* Alo = sm + 67584;
    char* Tc  = sm + 135168;
    float* ostg = (float*)(sm + 200704);   // 16 x 260 floats
    float* rqs  = (float*)(sm + 217344);   // 128
    float* rks  = rqs + 128;               // 256
    float* rsp  = rks + 256;               // 512
    float* rsum = rsp + 512;               // 128

    const int t = threadIdx.x;
    const int warp = t >> 5, lane = t & 31;
    const int mt = blockIdx.x;
    const int bh = blockIdx.y;
    const int head = bh & 7;
    const int b = bh >> 3;

    const __nv_bfloat16* gq = g_tokb + (size_t)bh * 256 * DDIM;
    const __nv_bfloat16* gk = g_tokb + (size_t)TOKB_PART + (size_t)bh * 256 * DDIM;
    const __nv_bfloat16* gv = g_tokb + 2u * (size_t)TOKB_PART + (size_t)bh * 256 * DDIM;
    const __nv_bfloat16* gvl = g_vlo + (size_t)bh * 256 * DDIM;

    const uint32_t aAh = smem_u32(Ahi);
    const uint32_t aAl = smem_u32(Alo);
    const uint32_t aV  = smem_u32(Tc);

    if (t < 128) {
        int n = (t >> 3) * 16 + mt * 8 + (t & 7);
        rqs[t] = g_rnorm[bh * 256 + n] * temperature[head];
    }
    rks[t] = g_rnorm[16384 + bh * 256 + t];

    const int warpM = warp >> 2, warpN = warp & 3;
    float acc[4][8][4];
#pragma unroll
    for (int i = 0; i < 4; i++)
#pragma unroll
        for (int j = 0; j < 8; j++)
#pragma unroll
            for (int q = 0; q < 4; q++) acc[i][j][q] = 0.f;

    // prologue: chunk 0 -> B0 (aV)
    {
#pragma unroll
        for (int i = 0; i < 4; i++) {
            int s = t + 256 * i; int r = s >> 3, cs = s & 7;
            int n = (r >> 3) * 16 + mt * 8 + (r & 7);
            cp16(aV + SW128(r * 128 + cs * 16), gq + (size_t)n * DDIM + cs * 8);
        }
#pragma unroll
        for (int i = 0; i < 8; i++) {
            int s = t + 256 * i; int m2 = s >> 3, cs = s & 7;
            cp16(aV + 16384 + SW128(m2 * 128 + cs * 16), gk + (size_t)m2 * DDIM + cs * 8);
        }
        CP_COMMIT();
    }

    // ---------------- Phase 1: S = Q K^T (pipelined) ----------------
#pragma unroll 1
    for (int ck = 0; ck < 24; ck++) {
        uint32_t aBuf = (ck & 1) ? aAh : aV;
        if (ck < 23) {
            int d0n = (ck + 1) * 64;
            uint32_t aNext = ((ck + 1) & 1) ? aAh : aV;
#pragma unroll
            for (int i = 0; i < 4; i++) {
                int s = t + 256 * i; int r = s >> 3, cs = s & 7;
                int n = (r >> 3) * 16 + mt * 8 + (r & 7);
                cp16(aNext + SW128(r * 128 + cs * 16), gq + (size_t)n * DDIM + d0n + cs * 8);
            }
#pragma unroll
            for (int i = 0; i < 8; i++) {
                int s = t + 256 * i; int m2 = s >> 3, cs = s & 7;
                cp16(aNext + 16384 + SW128(m2 * 128 + cs * 16),
                     gk + (size_t)m2 * DDIM + d0n + cs * 8);
            }
            CP_COMMIT();
            CP_WAIT1();
        } else {
            CP_WAIT0();
        }
        __syncthreads();

        int lm = lane & 15;
#pragma unroll
        for (int kk = 0; kk < 4; kk++) {
            int k0 = kk * 16;
            uint32_t af[4][4];
#pragma unroll
            for (int i = 0; i < 4; i++) {
                int row = warpM * 64 + i * 16 + lm;
                ldsm_x4(af[i], aBuf + SW128(row * 128 + k0 * 2 + ((lane >> 4) << 4)));
            }
            uint32_t bfg[8][2];
#pragma unroll
            for (int j = 0; j < 8; j++) {
                int row = warpN * 64 + j * 8 + (lm & 7);
                ldsm_x2(bfg[j], aBuf + 16384 + SW128(row * 128 + (k0 + ((lm >> 3) << 3)) * 2));
            }
#pragma unroll
            for (int i = 0; i < 4; i++)
#pragma unroll
                for (int j = 0; j < 8; j++) mma_bf16(acc[i][j], af[i], bfg[j]);
        }
        __syncthreads();
    }

    // -------- Epilogue 1: exp, rowsum, A -> smem hi+lo --------
#pragma unroll
    for (int i = 0; i < 4; i++) {
        int m0 = warpM * 64 + i * 16 + (lane >> 2);
        int m1 = m0 + 8;
        float q0 = rqs[m0], q1 = rqs[m1];
        float r0 = 0.f, r1 = 0.f;
#pragma unroll
        for (int j = 0; j < 8; j++) {
            int n0 = warpN * 64 + j * 8 + ((lane & 3) << 1);
            float k0v = rks[n0], k1v = rks[n0 + 1];
            float e00 = __expf(acc[i][j][0] * q0 * k0v);
            float e01 = __expf(acc[i][j][1] * q0 * k1v);
            float e10 = __expf(acc[i][j][2] * q1 * k0v);
            float e11 = __expf(acc[i][j][3] * q1 * k1v);
            r0 += e00 + e01; r1 += e10 + e11;
            uint32_t p0, p1;
            asm("cvt.rn.bf16x2.f32 %0, %1, %2;" : "=r"(p0) : "f"(e01), "f"(e00));
            asm("cvt.rn.bf16x2.f32 %0, %1, %2;" : "=r"(p1) : "f"(e11), "f"(e10));
            float h00 = __uint_as_float(p0 << 16),  h01 = __uint_as_float(p0 & 0xFFFF0000u);
            float h10 = __uint_as_float(p1 << 16),  h11 = __uint_as_float(p1 & 0xFFFF0000u);
            uint32_t q0p, q1p;
            asm("cvt.rn.bf16x2.f32 %0, %1, %2;" : "=r"(q0p) : "f"(e01 - h01), "f"(e00 - h00));
            asm("cvt.rn.bf16x2.f32 %0, %1, %2;" : "=r"(q1p) : "f"(e11 - h11), "f"(e10 - h10));
            *(uint32_t*)(Ahi + m0 * 528 + n0 * 2) = p0;
            *(uint32_t*)(Ahi + m1 * 528 + n0 * 2) = p1;
            *(uint32_t*)(Alo + m0 * 528 + n0 * 2) = q0p;
            *(uint32_t*)(Alo + m1 * 528 + n0 * 2) = q1p;
        }
        r0 += __shfl_xor_sync(0xffffffffu, r0, 1);
        r0 += __shfl_xor_sync(0xffffffffu, r0, 2);
        r1 += __shfl_xor_sync(0xffffffffu, r1, 1);
        r1 += __shfl_xor_sync(0xffffffffu, r1, 2);
        if ((lane & 3) == 0) {
            rsp[warpN * 128 + m0] = r0;
            rsp[warpN * 128 + m1] = r1;
        }
    }
    __syncthreads();
    if (t < 128) rsum[t] = 1.0f / (rsp[t] + rsp[128 + t] + rsp[256 + t] + rsp[384 + t] + 1.0f);
    __syncthreads();

    // -------- Phase 2: O = Ahi*Vhi + Ahi*Vlo + Alo*Vhi, pipelined 32-d --------
    float* oimg_base = g_oimg + ((size_t)(b * 48 + head * 6)) * HWSZ;
    const int fy0 = mt * 8;
    const int lm = lane & 15;
    const int m0r = warp * 16;

    // prologue: sub-chunk 0 -> stage 0
    {
#pragma unroll
        for (int i = 0; i < 4; i++) {
            int idx = t + 256 * i; int m2 = idx >> 2, cs = idx & 3;
            cp16(aV + SW64(m2 * 64 + cs * 16), gv + (size_t)m2 * DDIM + cs * 8);
            cp16(aV + 16384 + SW64(m2 * 64 + cs * 16), gvl + (size_t)m2 * DDIM + cs * 8);
        }
        CP_COMMIT();
    }

#pragma unroll 1
    for (int sc = 0; sc < 48; sc++) {
        uint32_t stage = aV + (sc & 1) * 32768;
        if (sc < 47) {
            int d0n = (sc + 1) * 32;
            uint32_t nstage = aV + ((sc + 1) & 1) * 32768;
#pragma unroll
            for (int i = 0; i < 4; i++) {
                int idx = t + 256 * i; int m2 = idx >> 2, cs = idx & 3;
                cp16(nstage + SW64(m2 * 64 + cs * 16), gv + (size_t)m2 * DDIM + d0n + cs * 8);
                cp16(nstage + 16384 + SW64(m2 * 64 + cs * 16),
                     gvl + (size_t)m2 * DDIM + d0n + cs * 8);
            }
            CP_COMMIT();
            CP_WAIT1();
        } else {
            CP_WAIT0();
        }
        __syncthreads();   // V(sc) ready; prev OSTG reads done

        float oacc[4][4];
#pragma unroll
        for (int j = 0; j < 4; j++)
#pragma unroll
            for (int q = 0; q < 4; q++) oacc[j][q] = 0.f;

#pragma unroll 1
        for (int kk = 0; kk < 16; kk++) {
            int n0 = kk * 16;
            uint32_t afh[4], afl[4];
            ldsm_x4(afh, aAh + (m0r + lm) * 528 + (n0 + ((lane >> 4) << 3)) * 2);
            ldsm_x4(afl, aAl + (m0r + lm) * 528 + (n0 + ((lane >> 4) << 3)) * 2);
#pragma unroll
            for (int j = 0; j < 4; j++) {
                uint32_t bh2[2], bl2[2];
                ldsm_x2t(bh2, stage + SW64((n0 + lm) * 64 + j * 16));
                ldsm_x2t(bl2, stage + 16384 + SW64((n0 + lm) * 64 + j * 16));
                mma_bf16(oacc[j], afh, bh2);
                mma_bf16(oacc[j], afh, bl2);
                mma_bf16(oacc[j], afl, bh2);
            }
        }

        // stage output (16 image rows) into OSTG
        {
            int r0 = m0r + (lane >> 2), r1 = r0 + 8;
            float s0 = rsum[r0], s1 = rsum[r1];
            int fx0 = r0 >> 3, fyl0 = r0 & 7;
            int fx1 = r1 >> 3, fyl1 = r1 & 7;
#pragma unroll
            for (int j = 0; j < 4; j++) {
                int cd = j * 8 + ((lane & 3) << 1);
                int hl = cd >> 4, ww = cd & 15;
                ostg[(hl * 8 + fyl0) * 260 + ww * 16 + fx0]       = oacc[j][0] * s0;
                ostg[(hl * 8 + fyl0) * 260 + (ww + 1) * 16 + fx0] = oacc[j][1] * s0;
                ostg[(hl * 8 + fyl1) * 260 + ww * 16 + fx1]       = oacc[j][2] * s1;
                ostg[(hl * 8 + fyl1) * 260 + (ww + 1) * 16 + fx1] = oacc[j][3] * s1;
            }
        }
        __syncthreads();   // OSTG complete

        int d0 = sc * 32;
        int c = d0 >> 8, hh0 = (d0 >> 4) & 15;
#pragma unroll
        for (int rr = 0; rr < 16; rr++) {
            int y = (hh0 + (rr >> 3)) * 16 + fy0 + (rr & 7);
            oimg_base[((size_t)c * 256 + y) * 256 + t] = ostg[rr * 260 + t];
        }
    }
}

// ---------------------------------------------------------------------------
// K4: project_out 1x1 conv (scalar, unchanged)
// ---------------------------------------------------------------------------
__global__ __launch_bounds__(256) void k_proj(const float* __restrict__ wp,
                                              float* __restrict__ out) {
    __shared__ float ws[48 * 48];
    __shared__ float xs[48 * 64];
    int t = threadIdx.x;
    int b = blockIdx.y;
    int p0 = blockIdx.x * 64;

    for (int i = t; i < 48 * 48; i += 256) ws[i] = wp[i];
    const float* xb = g_oimg + (size_t)b * 48 * HWSZ + p0;
    for (int i = t; i < 48 * 64; i += 256) {
        int c = i >> 6, px = i & 63;
        xs[c * 64 + px] = xb[(size_t)c * HWSZ + px];
    }
    __syncthreads();

    int pxg = t & 15, og = t >> 4;
    float acc[3][4];
#pragma unroll
    for (int j = 0; j < 3; j++)
#pragma unroll
        for (int ii = 0; ii < 4; ii++) acc[j][ii] = 0.f;

#pragma unroll 4
    for (int k = 0; k < 48; k++) {
        float4 xv = *reinterpret_cast<const float4*>(&xs[k * 64 + pxg * 4]);
#pragma unroll
        for (int j = 0; j < 3; j++) {
            float w = ws[(og * 3 + j) * 48 + k];
            acc[j][0] += w * xv.x; acc[j][1] += w * xv.y;
            acc[j][2] += w * xv.z; acc[j][3] += w * xv.w;
        }
    }
    float* ob = out + (size_t)b * 48 * HWSZ + p0 + pxg * 4;
#pragma unroll
    for (int j = 0; j < 3; j++) {
        int o = og * 3 + j;
        float4 v = make_float4(acc[j][0], acc[j][1], acc[j][2], acc[j][3]);
        *reinterpret_cast<float4*>(&ob[(size_t)o * HWSZ]) = v;
    }
}

extern "C" void kernel_launch(void* const* d_in, const int* in_sizes, int n_in,
                              void* d_out, int out_size) {
    const float* x      = (const float*)d_in[0];
    const float* w_qkv  = (const float*)d_in[1];
    const float* w_dw   = (const float*)d_in[2];
    const float* w_proj = (const float*)d_in[3];
    const float* temp   = (const float*)d_in[4];
    float* out = (float*)d_out;

    cudaFuncSetAttribute(k_attn, cudaFuncAttributeMaxDynamicSharedMemorySize, 221440);
    cudaFuncSetAttribute(k_qkv, cudaFuncAttributeMaxDynamicSharedMemorySize, 72 * 1024);

    k_qkv<<<dim3(512, 8), 256, 69632>>>(x, w_qkv);
    k_dw<<<dim3(144, 8, 8), 256>>>(w_dw);
    k_norm<<<4096, 256>>>();
    k_attn<<<dim3(2, 64), 256, 221440>>>(temp);
    k_proj<<<dim3(1024, 8), 256>>>(w_proj, out);
}